// round 13
// baseline (speedup 1.0000x reference)
#include <cuda_runtime.h>

#define B   8
#define EH  768
#define T   512
#define PH  320
#define U   128
#define JH  320
#define C   34
#define NT5 5          // n-tiles (N=40)
#define KS  40         // k8 steps (K=320)
#define EKH 384        // k_enc k-split chunk (2 parts)
#define PKH 80         // k_pred k-split chunk (4 parts)
#define N_E (B * T * JH)
#define N_P (B * (JH / 4) * U)

typedef unsigned long long u64;
typedef unsigned int u32;

// Scratch (device globals; no runtime allocation allowed)
__device__ float  g_Wt [EH * JH];            // W_enc transposed: [k][j]
__device__ float  g_Wpt[PH * JH];            // W_pred transposed: [k][j]
__device__ float  g_ep [2][N_E];             // e partials (k-split)
__device__ float  g_e  [N_E];                // e[b][t][j] (reduced)
__device__ float4 g_p4p[4][N_P];             // p partials (k-split)
__device__ float4 g_p4 [N_P];                // p interleaved [b][j4][u] (reduced)
__device__ float2 g_Wimg[NT5 * KS * 32];     // W_out tf32 fragment image

// ---- f32x2 packed helpers (projection kernels) ----------------------------
__device__ __forceinline__ u64 pack2(float lo, float hi) {
    u64 r; asm("mov.b64 %0, {%1, %2};" : "=l"(r) : "f"(lo), "f"(hi)); return r;
}
__device__ __forceinline__ void unpack2(u64 v, float& lo, float& hi) {
    asm("mov.b64 {%0, %1}, %2;" : "=f"(lo), "=f"(hi) : "l"(v));
}
#define FMA2(acc, a, b) \
    asm("fma.rn.f32x2 %0, %1, %2, %0;" : "+l"(acc) : "l"(a), "l"(b))
__device__ __forceinline__ void lds_2x64(u64& a, u64& b, const float* p) {
    u32 sa;
    asm("{ .reg .u64 t; cvta.to.shared.u64 t, %1; cvt.u32.u64 %0, t; }"
        : "=r"(sa) : "l"(p));
    asm("ld.shared.v2.u64 {%0, %1}, [%2];" : "=l"(a), "=l"(b) : "r"(sa));
}

// ---- tf32 mma helpers -----------------------------------------------------
__device__ __forceinline__ u32 cvt_tf32(float f) {
    u32 r; asm("cvt.rna.tf32.f32 %0, %1;" : "=r"(r) : "f"(f)); return r;
}
#define MMA_TF32(d, a0, a1, a2, a3, b0, b1)                                   \
    asm("mma.sync.aligned.m16n8k8.row.col.f32.tf32.tf32.f32 "                 \
        "{%0,%1,%2,%3}, {%4,%5,%6,%7}, {%8,%9}, {%0,%1,%2,%3};"               \
        : "+f"((d)[0]), "+f"((d)[1]), "+f"((d)[2]), "+f"((d)[3])              \
        : "r"(a0), "r"(a1), "r"(a2), "r"(a3), "r"(b0), "r"(b1))

// FMA-pipe exp (no MUFU): valid for x <= 0, rel err ~2.4e-6
__device__ __forceinline__ float fexp(float x) {
    x = fmaxf(x, -80.f);
    float y = x * 1.4426950408889634f;
    float r = rintf(y);
    float t = (y - r) * 0.6931471805599453f;
    float p = 8.3333333e-3f;
    p = fmaf(p, t, 4.1666667e-2f);
    p = fmaf(p, t, 1.6666667e-1f);
    p = fmaf(p, t, 5.0e-1f);
    p = fmaf(p, t, 1.0f);
    p = fmaf(p, t, 1.0f);
    int ni = (int)r;
    float sc = __uint_as_float((u32)(ni + 127) << 23);
    return p * sc;
}

// ---------------------------------------------------------------------------
// K0: tiled transpose (coalesced both sides). z=0: W_enc, z=1: W_pred.
// ---------------------------------------------------------------------------
__global__ void k_transpose(const float* __restrict__ W_enc,
                            const float* __restrict__ W_pred) {
    __shared__ float tile[32][33];
    const int which = blockIdx.z;
    const float* src = which ? W_pred : W_enc;
    float* dst = which ? g_Wpt : g_Wt;
    const int Kdim = which ? PH : EH;
    const int k0 = blockIdx.x * 32, j0 = blockIdx.y * 32;
    if (k0 >= Kdim) return;
    const int tx = threadIdx.x, ty = threadIdx.y;
#pragma unroll
    for (int dy = 0; dy < 32; dy += 8)
        tile[ty + dy][tx] = src[(size_t)(j0 + ty + dy) * Kdim + k0 + tx];
    __syncthreads();
#pragma unroll
    for (int dy = 0; dy < 32; dy += 8)
        dst[(size_t)(k0 + ty + dy) * JH + j0 + tx] = tile[tx][ty + dy];
}

// ---------------------------------------------------------------------------
// K0b: bake W_out (padded to 40 rows) into mma B-fragment layout, tf32-rounded.
// ---------------------------------------------------------------------------
__global__ void k_wprep(const float* __restrict__ W_out) {
    int i = blockIdx.x * blockDim.x + threadIdx.x;
    if (i >= NT5 * KS * 32) return;
    int lane = i & 31;
    int ks = (i >> 5) % KS;
    int nt = i / (KS * 32);
    int g = lane >> 2, cq = lane & 3;
    int n = nt * 8 + g;
    int k0 = ks * 8;
    float v0 = (n < C) ? W_out[n * JH + k0 + cq]     : 0.f;
    float v1 = (n < C) ? W_out[n * JH + k0 + cq + 4] : 0.f;
    g_Wimg[i] = make_float2(__uint_as_float(cvt_tf32(v0)),
                            __uint_as_float(cvt_tf32(v1)));
}

// ---------------------------------------------------------------------------
// K1: e projection, k-split x2.  CTA = (part, b, 16 t). 320 threads = j.
// ---------------------------------------------------------------------------
__global__ __launch_bounds__(320) void k_enc(const float* __restrict__ enc,
                                             const float* __restrict__ b_enc) {
    __shared__ float enc_s[EKH * 16];   // 24 KB
    const int bx = blockIdx.x;
    const int part = bx >> 8;
    const int rem  = bx & 255;
    const int b = rem >> 5, t0 = (rem & 31) << 4, tid = threadIdx.x;
    const int kbase = part * EKH;

    const float* src = enc + (size_t)b * EH * T + (size_t)kbase * T + t0;
    for (int i = tid; i < EKH * 16; i += 320) {
        int k = i >> 4, t = i & 15;
        enc_s[i] = src[k * T + t];
    }
    __syncthreads();

    const int j = tid;
    u64 acc[8];
    {
        float bj = part ? 0.f : b_enc[j];
        u64 b2 = pack2(bj, bj);
#pragma unroll
        for (int m = 0; m < 8; m++) acc[m] = b2;
    }

#pragma unroll 1
    for (int k = 0; k < EKH; k += 4) {
#pragma unroll
        for (int kk = 0; kk < 4; kk++) {
            float w = g_Wt[(kbase + k + kk) * JH + j];
            u64 wp = pack2(w, w);
            const float* er = &enc_s[(k + kk) * 16];
            u64 e0, e1, e2, e3, e4, e5, e6, e7;
            lds_2x64(e0, e1, er);
            lds_2x64(e2, e3, er + 4);
            lds_2x64(e4, e5, er + 8);
            lds_2x64(e6, e7, er + 12);
            FMA2(acc[0], wp, e0);  FMA2(acc[1], wp, e1);
            FMA2(acc[2], wp, e2);  FMA2(acc[3], wp, e3);
            FMA2(acc[4], wp, e4);  FMA2(acc[5], wp, e5);
            FMA2(acc[6], wp, e6);  FMA2(acc[7], wp, e7);
        }
    }

    float* dst = g_ep[part] + ((size_t)b * T + t0) * JH + j;
#pragma unroll
    for (int m = 0; m < 8; m++) {
        float lo, hi; unpack2(acc[m], lo, hi);
        dst[(2 * m) * JH] = lo; dst[(2 * m + 1) * JH] = hi;
    }
}

// ---------------------------------------------------------------------------
// K2: p projection, k-split x4. CTA = (part, b, 8 u). 320 threads = j.
// ---------------------------------------------------------------------------
__global__ __launch_bounds__(320) void k_pred(const float* __restrict__ dec,
                                              const float* __restrict__ b_pred) {
    __shared__ float dec_s[PKH * 8];
    const int bx = blockIdx.x;
    const int part = bx >> 7;
    const int rem  = bx & 127;
    const int b = rem >> 4, u0 = (rem & 15) << 3, tid = threadIdx.x;
    const int kbase = part * PKH;

    const float* src = dec + (size_t)b * PH * U + (size_t)kbase * U + u0;
    for (int i = tid; i < PKH * 8; i += 320) {
        int k = i >> 3, uu = i & 7;
        dec_s[i] = src[k * U + uu];
    }
    __syncthreads();

    const int j = tid;
    u64 acc[4];
    {
        float bj = part ? 0.f : b_pred[j];
        u64 b2 = pack2(bj, bj);
#pragma unroll
        for (int m = 0; m < 4; m++) acc[m] = b2;
    }

#pragma unroll 1
    for (int k = 0; k < PKH; k += 4) {
#pragma unroll
        for (int kk = 0; kk < 4; kk++) {
            float w = g_Wpt[(kbase + k + kk) * JH + j];
            u64 wp = pack2(w, w);
            const float* dr = &dec_s[(k + kk) * 8];
            u64 d0, d1, d2, d3;
            lds_2x64(d0, d1, dr);
            lds_2x64(d2, d3, dr + 4);
            FMA2(acc[0], wp, d0);  FMA2(acc[1], wp, d1);
            FMA2(acc[2], wp, d2);  FMA2(acc[3], wp, d3);
        }
    }

    float* p4f = (float*)g_p4p[part];
    const int base = ((b * (JH / 4) + (j >> 2)) * U) * 4 + (j & 3);
#pragma unroll
    for (int m = 0; m < 4; m++) {
        float lo, hi; unpack2(acc[m], lo, hi);
        p4f[base + (u0 + 2 * m) * 4]     = lo;
        p4f[base + (u0 + 2 * m + 1) * 4] = hi;
    }
}

// ---------------------------------------------------------------------------
// K2b: reduce k-split partials: g_e = ep0+ep1 ; g_p4 = sum of 4 parts
// ---------------------------------------------------------------------------
__global__ void k_reduce() {
    int i = blockIdx.x * 256 + threadIdx.x;
    if (i < N_E) g_e[i] = g_ep[0][i] + g_ep[1][i];
    if (i < N_P) {
        float4 a = g_p4p[0][i], b = g_p4p[1][i], c = g_p4p[2][i], d = g_p4p[3][i];
        g_p4[i] = make_float4(a.x + b.x + c.x + d.x, a.y + b.y + c.y + d.y,
                              a.z + b.z + c.z + d.z, a.w + b.w + c.w + d.w);
    }
}

// ---------------------------------------------------------------------------
// K3 (main): tensor-core joint. CTA covers 16t x 32u as TWO sequential 16-u
// halves (W + e staged once, p re-staged per half). 128 thr / 4 warps.
// ---------------------------------------------------------------------------
#define ESTRIDE 324
#define SM_W 0
#define SM_E (NT5 * KS * 32 * 2)               // 12800 floats
#define SM_P (SM_E + 16 * ESTRIDE)
#define SM_FLOATS (SM_P + 16 * ESTRIDE)        // 23168 floats = 92672 B

__global__ __launch_bounds__(128) void k_main(const float* __restrict__ b_out,
                                              float* __restrict__ out) {
    extern __shared__ float sm[];
    float* W_s = sm + SM_W;
    float* e_s = sm + SM_E;
    float* p_s = sm + SM_P;

    const int tid = threadIdx.x;
    const int lane = tid & 31, w = tid >> 5;
    const int g = lane >> 2, cq = lane & 3;

    const int bx = blockIdx.x;                 // 1024 = 8b x 32tt x 4up
    const int b  = bx >> 7;
    const int t0 = ((bx >> 2) & 31) << 4;
    const int u0base = (bx & 3) << 5;

    // ---- stage W frags + e rows (once per CTA) ----
    {
        const float4* Wd = (const float4*)g_Wimg;
        float4* Ws4 = (float4*)W_s;
        for (int i = tid; i < NT5 * KS * 16; i += 128) Ws4[i] = Wd[i];

        const float* esrc = g_e + ((size_t)b * T + t0) * JH;
        for (int i = tid; i < 16 * 80; i += 128) {
            int r = i / 80, q = i % 80;
            ((float4*)&e_s[r * ESTRIDE])[q] = ((const float4*)&esrc[(size_t)r * JH])[q];
        }
    }

    // bias frags (constant across halves)
    float bo[NT5][2];
#pragma unroll
    for (int nt = 0; nt < NT5; nt++) {
        int cls = nt * 8 + 2 * cq;
        bo[nt][0] = (cls     < C) ? __ldg(&b_out[cls])     : 0.f;
        bo[nt][1] = (cls + 1 < C) ? __ldg(&b_out[cls + 1]) : 0.f;
    }
    const bool val4 = (cq == 0);

#pragma unroll 1
    for (int half = 0; half < 2; half++) {
        const int u0 = u0base + (half << 4);

        if (half) __syncthreads();             // prior compute done before re-stage
        {
            const float4* psrc = g_p4 + (size_t)b * (JH / 4) * U + u0;
            for (int i = tid; i < 16 * 80; i += 128) {
                int q = i >> 4, r = i & 15;    // q = j4, r = u
                ((float4*)&p_s[r * ESTRIDE])[q] = psrc[q * U + r];
            }
        }
        __syncthreads();

        float acc[4][NT5][4];
#pragma unroll
        for (int mt = 0; mt < 4; mt++)
#pragma unroll
            for (int nt = 0; nt < NT5; nt++)
#pragma unroll
                for (int i = 0; i < 4; i++) acc[mt][nt][i] = 0.f;

        // ---- main k loop ----
#pragma unroll 1
        for (int ks = 0; ks < KS; ks++) {
            const int k0 = ks * 8;
            u32 bf[NT5][2];
#pragma unroll
            for (int nt = 0; nt < NT5; nt++) {
                float2 bv = *(const float2*)&W_s[((nt * KS + ks) * 32 + lane) * 2];
                bf[nt][0] = __float_as_uint(bv.x);
                bf[nt][1] = __float_as_uint(bv.y);
            }
            // p values hoisted out of mt loop
            const float* pr0 = &p_s[g * ESTRIDE + k0];
            const float* pr1 = &p_s[(g + 8) * ESTRIDE + k0];
            const float p00 = pr0[cq], p01 = pr0[cq + 4];
            const float p10 = pr1[cq], p11 = pr1[cq + 4];
#pragma unroll
            for (int mt = 0; mt < 4; mt++) {
                const float* er = &e_s[(4 * w + mt) * ESTRIDE + k0];
                float e0 = er[cq], e1 = er[cq + 4];
                u32 a0 = cvt_tf32(fmaxf(e0 + p00, 0.f));   // (r, cq)
                u32 a1 = cvt_tf32(fmaxf(e0 + p10, 0.f));   // (r+8, cq)
                u32 a2 = cvt_tf32(fmaxf(e1 + p01, 0.f));   // (r, cq+4)
                u32 a3 = cvt_tf32(fmaxf(e1 + p11, 0.f));   // (r+8, cq+4)
#pragma unroll
                for (int nt = 0; nt < NT5; nt++)
                    MMA_TF32(acc[mt][nt], a0, a1, a2, a3, bf[nt][0], bf[nt][1]);
            }
        }

        // ---- epilogue: bias + masked log_softmax + store ----
#pragma unroll 1
        for (int mt = 0; mt < 4; mt++) {
            float lA[NT5][2], lB[NT5][2];
#pragma unroll
            for (int nt = 0; nt < NT5; nt++) {
                lA[nt][0] = acc[mt][nt][0] + bo[nt][0];
                lA[nt][1] = acc[mt][nt][1] + bo[nt][1];
                lB[nt][0] = acc[mt][nt][2] + bo[nt][0];
                lB[nt][1] = acc[mt][nt][3] + bo[nt][1];
            }
            float mA = -1e30f, mB = -1e30f;
#pragma unroll
            for (int nt = 0; nt < 4; nt++) {
                mA = fmaxf(mA, fmaxf(lA[nt][0], lA[nt][1]));
                mB = fmaxf(mB, fmaxf(lB[nt][0], lB[nt][1]));
            }
            if (val4) {
                mA = fmaxf(mA, fmaxf(lA[4][0], lA[4][1]));
                mB = fmaxf(mB, fmaxf(lB[4][0], lB[4][1]));
            }
            mA = fmaxf(mA, __shfl_xor_sync(0xffffffffu, mA, 1));
            mA = fmaxf(mA, __shfl_xor_sync(0xffffffffu, mA, 2));
            mB = fmaxf(mB, __shfl_xor_sync(0xffffffffu, mB, 1));
            mB = fmaxf(mB, __shfl_xor_sync(0xffffffffu, mB, 2));

            float sA = 0.f, sB = 0.f;
#pragma unroll
            for (int nt = 0; nt < 4; nt++) {
                sA += fexp(lA[nt][0] - mA) + fexp(lA[nt][1] - mA);
                sB += fexp(lB[nt][0] - mB) + fexp(lB[nt][1] - mB);
            }
            if (val4) {
                sA += fexp(lA[4][0] - mA) + fexp(lA[4][1] - mA);
                sB += fexp(lB[4][0] - mB) + fexp(lB[4][1] - mB);
            }
            sA += __shfl_xor_sync(0xffffffffu, sA, 1);
            sA += __shfl_xor_sync(0xffffffffu, sA, 2);
            sB += __shfl_xor_sync(0xffffffffu, sB, 1);
            sB += __shfl_xor_sync(0xffffffffu, sB, 2);

            float lseA = 0.f, lseB = 0.f;
            if (cq == 0) { lseA = mA + logf(sA); lseB = mB + logf(sB); }
            lseA = __shfl_sync(0xffffffffu, lseA, lane & ~3);
            lseB = __shfl_sync(0xffffffffu, lseB, lane & ~3);

            const int tglob = t0 + 4 * w + mt;
            float* oA = out + (((size_t)(b * T + tglob)) * U + u0 + g) * C;
            float* oB = oA + 8 * C;            // u + 8
#pragma unroll
            for (int nt = 0; nt < 4; nt++) {
                *(float2*)&oA[nt * 8 + 2 * cq] = make_float2(lA[nt][0] - lseA, lA[nt][1] - lseA);
                *(float2*)&oB[nt * 8 + 2 * cq] = make_float2(lB[nt][0] - lseB, lB[nt][1] - lseB);
            }
            if (val4) {
                *(float2*)&oA[32] = make_float2(lA[4][0] - lseA, lA[4][1] - lseA);
                *(float2*)&oB[32] = make_float2(lB[4][0] - lseB, lB[4][1] - lseB);
            }
        }
    }
}

// ---------------------------------------------------------------------------
extern "C" void kernel_launch(void* const* d_in, const int* in_sizes, int n_in,
                              void* d_out, int out_size) {
    const float* enc    = (const float*)d_in[0];
    const float* dec    = (const float*)d_in[1];
    const float* W_enc  = (const float*)d_in[2];
    const float* b_enc  = (const float*)d_in[3];
    const float* W_pred = (const float*)d_in[4];
    const float* b_pred = (const float*)d_in[5];
    const float* W_out  = (const float*)d_in[6];
    const float* b_out  = (const float*)d_in[7];
    float* out = (float*)d_out;

    static bool attr_set = false;
    if (!attr_set) {
        cudaFuncSetAttribute(k_main, cudaFuncAttributeMaxDynamicSharedMemorySize,
                             SM_FLOATS * 4);
        attr_set = true;
    }

    k_transpose<<<dim3(24, 10, 2), dim3(32, 8)>>>(W_enc, W_pred);
    k_wprep<<<(NT5 * KS * 32 + 255) / 256, 256>>>(W_out);
    k_enc <<<2 * B * (T / 16), 320>>>(enc, b_enc);
    k_pred<<<4 * B * (U / 8),  320>>>(dec, b_pred);
    k_reduce<<<(N_E + 255) / 256, 256>>>();
    k_main<<<B * (T / 16) * (U / 32), 128, SM_FLOATS * 4>>>(b_out, out);
}

// round 14
// speedup vs baseline: 1.0227x; 1.0227x over previous
#include <cuda_runtime.h>

#define B   8
#define EH  768
#define T   512
#define PH  320
#define U   128
#define JH  320
#define C   34
#define NT5 5          // n-tiles (N=40)
#define KS  40         // k8 steps (K=320)
#define EKH 384        // k_enc k-split chunk (2 parts)
#define PKH 80         // k_pred k-split chunk (4 parts)
#define N_E (B * T * JH)
#define N_P (B * (JH / 4) * U)

typedef unsigned long long u64;
typedef unsigned int u32;

// Scratch (device globals; no runtime allocation allowed)
__device__ float  g_Wt [EH * JH];            // W_enc transposed: [k][j]
__device__ float  g_Wpt[PH * JH];            // W_pred transposed: [k][j]
__device__ float  g_ep [2][N_E];             // e partials (k-split)
__device__ float  g_e  [N_E];                // e[b][t][j] (reduced)
__device__ float4 g_p4p[4][N_P];             // p partials (k-split)
__device__ float4 g_p4 [N_P];                // p interleaved [b][j4][u] (reduced)
__device__ float2 g_Wimg[NT5 * KS * 32];     // W_out tf32 fragment image

// ---- f32x2 packed helpers (projection kernels) ----------------------------
__device__ __forceinline__ u64 pack2(float lo, float hi) {
    u64 r; asm("mov.b64 %0, {%1, %2};" : "=l"(r) : "f"(lo), "f"(hi)); return r;
}
__device__ __forceinline__ void unpack2(u64 v, float& lo, float& hi) {
    asm("mov.b64 {%0, %1}, %2;" : "=f"(lo), "=f"(hi) : "l"(v));
}
#define FMA2(acc, a, b) \
    asm("fma.rn.f32x2 %0, %1, %2, %0;" : "+l"(acc) : "l"(a), "l"(b))
__device__ __forceinline__ void lds_2x64(u64& a, u64& b, const float* p) {
    u32 sa;
    asm("{ .reg .u64 t; cvta.to.shared.u64 t, %1; cvt.u32.u64 %0, t; }"
        : "=r"(sa) : "l"(p));
    asm("ld.shared.v2.u64 {%0, %1}, [%2];" : "=l"(a), "=l"(b) : "r"(sa));
}

// ---- tf32 mma helpers -----------------------------------------------------
__device__ __forceinline__ u32 cvt_tf32(float f) {
    u32 r; asm("cvt.rna.tf32.f32 %0, %1;" : "=r"(r) : "f"(f)); return r;
}
#define MMA_TF32(d, a0, a1, a2, a3, b0, b1)                                   \
    asm("mma.sync.aligned.m16n8k8.row.col.f32.tf32.tf32.f32 "                 \
        "{%0,%1,%2,%3}, {%4,%5,%6,%7}, {%8,%9}, {%0,%1,%2,%3};"               \
        : "+f"((d)[0]), "+f"((d)[1]), "+f"((d)[2]), "+f"((d)[3])              \
        : "r"(a0), "r"(a1), "r"(a2), "r"(a3), "r"(b0), "r"(b1))

// FMA-pipe exp (no MUFU): valid for x <= 0, rel err ~2.4e-6
__device__ __forceinline__ float fexp(float x) {
    x = fmaxf(x, -80.f);
    float y = x * 1.4426950408889634f;
    float r = rintf(y);
    float t = (y - r) * 0.6931471805599453f;
    float p = 8.3333333e-3f;
    p = fmaf(p, t, 4.1666667e-2f);
    p = fmaf(p, t, 1.6666667e-1f);
    p = fmaf(p, t, 5.0e-1f);
    p = fmaf(p, t, 1.0f);
    p = fmaf(p, t, 1.0f);
    int ni = (int)r;
    float sc = __uint_as_float((u32)(ni + 127) << 23);
    return p * sc;
}

// ---------------------------------------------------------------------------
// K0: tiled transpose (coalesced both sides). z=0: W_enc, z=1: W_pred.
// ---------------------------------------------------------------------------
__global__ void k_transpose(const float* __restrict__ W_enc,
                            const float* __restrict__ W_pred) {
    __shared__ float tile[32][33];
    const int which = blockIdx.z;
    const float* src = which ? W_pred : W_enc;
    float* dst = which ? g_Wpt : g_Wt;
    const int Kdim = which ? PH : EH;
    const int k0 = blockIdx.x * 32, j0 = blockIdx.y * 32;
    if (k0 >= Kdim) return;
    const int tx = threadIdx.x, ty = threadIdx.y;
#pragma unroll
    for (int dy = 0; dy < 32; dy += 8)
        tile[ty + dy][tx] = src[(size_t)(j0 + ty + dy) * Kdim + k0 + tx];
    __syncthreads();
#pragma unroll
    for (int dy = 0; dy < 32; dy += 8)
        dst[(size_t)(k0 + ty + dy) * JH + j0 + tx] = tile[tx][ty + dy];
}

// ---------------------------------------------------------------------------
// K0b: bake W_out (padded to 40 rows) into mma B-fragment layout, tf32-rounded.
// ---------------------------------------------------------------------------
__global__ void k_wprep(const float* __restrict__ W_out) {
    int i = blockIdx.x * blockDim.x + threadIdx.x;
    if (i >= NT5 * KS * 32) return;
    int lane = i & 31;
    int ks = (i >> 5) % KS;
    int nt = i / (KS * 32);
    int g = lane >> 2, cq = lane & 3;
    int n = nt * 8 + g;
    int k0 = ks * 8;
    float v0 = (n < C) ? W_out[n * JH + k0 + cq]     : 0.f;
    float v1 = (n < C) ? W_out[n * JH + k0 + cq + 4] : 0.f;
    g_Wimg[i] = make_float2(__uint_as_float(cvt_tf32(v0)),
                            __uint_as_float(cvt_tf32(v1)));
}

// ---------------------------------------------------------------------------
// K1: e projection, k-split x2.  CTA = (part, b, 16 t). 320 threads = j.
// ---------------------------------------------------------------------------
__global__ __launch_bounds__(320) void k_enc(const float* __restrict__ enc,
                                             const float* __restrict__ b_enc) {
    __shared__ float enc_s[EKH * 16];   // 24 KB
    const int bx = blockIdx.x;
    const int part = bx >> 8;
    const int rem  = bx & 255;
    const int b = rem >> 5, t0 = (rem & 31) << 4, tid = threadIdx.x;
    const int kbase = part * EKH;

    const float* src = enc + (size_t)b * EH * T + (size_t)kbase * T + t0;
    for (int i = tid; i < EKH * 16; i += 320) {
        int k = i >> 4, t = i & 15;
        enc_s[i] = src[k * T + t];
    }
    __syncthreads();

    const int j = tid;
    u64 acc[8];
    {
        float bj = part ? 0.f : b_enc[j];
        u64 b2 = pack2(bj, bj);
#pragma unroll
        for (int m = 0; m < 8; m++) acc[m] = b2;
    }

#pragma unroll 1
    for (int k = 0; k < EKH; k += 4) {
#pragma unroll
        for (int kk = 0; kk < 4; kk++) {
            float w = g_Wt[(kbase + k + kk) * JH + j];
            u64 wp = pack2(w, w);
            const float* er = &enc_s[(k + kk) * 16];
            u64 e0, e1, e2, e3, e4, e5, e6, e7;
            lds_2x64(e0, e1, er);
            lds_2x64(e2, e3, er + 4);
            lds_2x64(e4, e5, er + 8);
            lds_2x64(e6, e7, er + 12);
            FMA2(acc[0], wp, e0);  FMA2(acc[1], wp, e1);
            FMA2(acc[2], wp, e2);  FMA2(acc[3], wp, e3);
            FMA2(acc[4], wp, e4);  FMA2(acc[5], wp, e5);
            FMA2(acc[6], wp, e6);  FMA2(acc[7], wp, e7);
        }
    }

    float* dst = g_ep[part] + ((size_t)b * T + t0) * JH + j;
#pragma unroll
    for (int m = 0; m < 8; m++) {
        float lo, hi; unpack2(acc[m], lo, hi);
        dst[(2 * m) * JH] = lo; dst[(2 * m + 1) * JH] = hi;
    }
}

// ---------------------------------------------------------------------------
// K2: p projection, k-split x4. CTA = (part, b, 8 u). 320 threads = j.
// ---------------------------------------------------------------------------
__global__ __launch_bounds__(320) void k_pred(const float* __restrict__ dec,
                                              const float* __restrict__ b_pred) {
    __shared__ float dec_s[PKH * 8];
    const int bx = blockIdx.x;
    const int part = bx >> 7;
    const int rem  = bx & 127;
    const int b = rem >> 4, u0 = (rem & 15) << 3, tid = threadIdx.x;
    const int kbase = part * PKH;

    const float* src = dec + (size_t)b * PH * U + (size_t)kbase * U + u0;
    for (int i = tid; i < PKH * 8; i += 320) {
        int k = i >> 3, uu = i & 7;
        dec_s[i] = src[k * U + uu];
    }
    __syncthreads();

    const int j = tid;
    u64 acc[4];
    {
        float bj = part ? 0.f : b_pred[j];
        u64 b2 = pack2(bj, bj);
#pragma unroll
        for (int m = 0; m < 4; m++) acc[m] = b2;
    }

#pragma unroll 1
    for (int k = 0; k < PKH; k += 4) {
#pragma unroll
        for (int kk = 0; kk < 4; kk++) {
            float w = g_Wpt[(kbase + k + kk) * JH + j];
            u64 wp = pack2(w, w);
            const float* dr = &dec_s[(k + kk) * 8];
            u64 d0, d1, d2, d3;
            lds_2x64(d0, d1, dr);
            lds_2x64(d2, d3, dr + 4);
            FMA2(acc[0], wp, d0);  FMA2(acc[1], wp, d1);
            FMA2(acc[2], wp, d2);  FMA2(acc[3], wp, d3);
        }
    }

    float* p4f = (float*)g_p4p[part];
    const int base = ((b * (JH / 4) + (j >> 2)) * U) * 4 + (j & 3);
#pragma unroll
    for (int m = 0; m < 4; m++) {
        float lo, hi; unpack2(acc[m], lo, hi);
        p4f[base + (u0 + 2 * m) * 4]     = lo;
        p4f[base + (u0 + 2 * m + 1) * 4] = hi;
    }
}

// ---------------------------------------------------------------------------
// K2b: reduce k-split partials: g_e = ep0+ep1 ; g_p4 = sum of 4 parts
// ---------------------------------------------------------------------------
__global__ void k_reduce() {
    int i = blockIdx.x * 256 + threadIdx.x;
    if (i < N_E) g_e[i] = g_ep[0][i] + g_ep[1][i];
    if (i < N_P) {
        float4 a = g_p4p[0][i], b = g_p4p[1][i], c = g_p4p[2][i], d = g_p4p[3][i];
        g_p4[i] = make_float4(a.x + b.x + c.x + d.x, a.y + b.y + c.y + d.y,
                              a.z + b.z + c.z + d.z, a.w + b.w + c.w + d.w);
    }
}

// ---------------------------------------------------------------------------
// K3 (main): tensor-core joint. CTA = 16t x 16u (256 rows), 128 thr / 4 warps.
// (R12 single-tile structure — the 2-half variant regressed — plus the
//  p-operand hoist out of the mt loop.)
// ---------------------------------------------------------------------------
#define ESTRIDE 324
#define SM_W 0
#define SM_E (NT5 * KS * 32 * 2)               // 12800 floats
#define SM_P (SM_E + 16 * ESTRIDE)
#define SM_FLOATS (SM_P + 16 * ESTRIDE)        // 23168 floats = 92672 B

__global__ __launch_bounds__(128) void k_main(const float* __restrict__ b_out,
                                              float* __restrict__ out) {
    extern __shared__ float sm[];
    float* W_s = sm + SM_W;
    float* e_s = sm + SM_E;
    float* p_s = sm + SM_P;

    const int tid = threadIdx.x;
    const int lane = tid & 31, w = tid >> 5;
    const int g = lane >> 2, cq = lane & 3;

    const int bx = blockIdx.x;                 // 2048 = 8b x 32tt x 8ut
    const int b  = bx >> 8;
    const int t0 = ((bx >> 3) & 31) << 4;
    const int u0 = (bx & 7) << 4;

    // ---- stage W frags, e rows, p rows ----
    {
        const float4* Wd = (const float4*)g_Wimg;
        float4* Ws4 = (float4*)W_s;
        for (int i = tid; i < NT5 * KS * 16; i += 128) Ws4[i] = Wd[i];

        const float* esrc = g_e + ((size_t)b * T + t0) * JH;
        for (int i = tid; i < 16 * 80; i += 128) {
            int r = i / 80, q = i % 80;
            ((float4*)&e_s[r * ESTRIDE])[q] = ((const float4*)&esrc[(size_t)r * JH])[q];
        }
        const float4* psrc = g_p4 + (size_t)b * (JH / 4) * U + u0;
        for (int i = tid; i < 16 * 80; i += 128) {
            int q = i >> 4, r = i & 15;        // q = j4, r = u
            ((float4*)&p_s[r * ESTRIDE])[q] = psrc[q * U + r];
        }
    }
    __syncthreads();

    float acc[4][NT5][4];
#pragma unroll
    for (int mt = 0; mt < 4; mt++)
#pragma unroll
        for (int nt = 0; nt < NT5; nt++)
#pragma unroll
            for (int i = 0; i < 4; i++) acc[mt][nt][i] = 0.f;

    // ---- main k loop ----
#pragma unroll 1
    for (int ks = 0; ks < KS; ks++) {
        const int k0 = ks * 8;
        u32 bf[NT5][2];
#pragma unroll
        for (int nt = 0; nt < NT5; nt++) {
            float2 bv = *(const float2*)&W_s[((nt * KS + ks) * 32 + lane) * 2];
            bf[nt][0] = __float_as_uint(bv.x);
            bf[nt][1] = __float_as_uint(bv.y);
        }
        // p values hoisted out of mt loop
        const float* pr0 = &p_s[g * ESTRIDE + k0];
        const float* pr1 = &p_s[(g + 8) * ESTRIDE + k0];
        const float p00 = pr0[cq], p01 = pr0[cq + 4];
        const float p10 = pr1[cq], p11 = pr1[cq + 4];
#pragma unroll
        for (int mt = 0; mt < 4; mt++) {
            const float* er = &e_s[(4 * w + mt) * ESTRIDE + k0];
            float e0 = er[cq], e1 = er[cq + 4];
            u32 a0 = cvt_tf32(fmaxf(e0 + p00, 0.f));   // (r, cq)
            u32 a1 = cvt_tf32(fmaxf(e0 + p10, 0.f));   // (r+8, cq)
            u32 a2 = cvt_tf32(fmaxf(e1 + p01, 0.f));   // (r, cq+4)
            u32 a3 = cvt_tf32(fmaxf(e1 + p11, 0.f));   // (r+8, cq+4)
#pragma unroll
            for (int nt = 0; nt < NT5; nt++)
                MMA_TF32(acc[mt][nt], a0, a1, a2, a3, bf[nt][0], bf[nt][1]);
        }
    }

    // ---- epilogue: bias + masked log_softmax + store ----
    const bool val4 = (cq == 0);               // nt=4 classes {32,33} only on cq==0
    float bo[NT5][2];
#pragma unroll
    for (int nt = 0; nt < NT5; nt++) {
        int cls = nt * 8 + 2 * cq;
        bo[nt][0] = (cls     < C) ? __ldg(&b_out[cls])     : 0.f;
        bo[nt][1] = (cls + 1 < C) ? __ldg(&b_out[cls + 1]) : 0.f;
    }

#pragma unroll 1
    for (int mt = 0; mt < 4; mt++) {
        float lA[NT5][2], lB[NT5][2];
#pragma unroll
        for (int nt = 0; nt < NT5; nt++) {
            lA[nt][0] = acc[mt][nt][0] + bo[nt][0];
            lA[nt][1] = acc[mt][nt][1] + bo[nt][1];
            lB[nt][0] = acc[mt][nt][2] + bo[nt][0];
            lB[nt][1] = acc[mt][nt][3] + bo[nt][1];
        }
        float mA = -1e30f, mB = -1e30f;
#pragma unroll
        for (int nt = 0; nt < 4; nt++) {
            mA = fmaxf(mA, fmaxf(lA[nt][0], lA[nt][1]));
            mB = fmaxf(mB, fmaxf(lB[nt][0], lB[nt][1]));
        }
        if (val4) {
            mA = fmaxf(mA, fmaxf(lA[4][0], lA[4][1]));
            mB = fmaxf(mB, fmaxf(lB[4][0], lB[4][1]));
        }
        mA = fmaxf(mA, __shfl_xor_sync(0xffffffffu, mA, 1));
        mA = fmaxf(mA, __shfl_xor_sync(0xffffffffu, mA, 2));
        mB = fmaxf(mB, __shfl_xor_sync(0xffffffffu, mB, 1));
        mB = fmaxf(mB, __shfl_xor_sync(0xffffffffu, mB, 2));

        float sA = 0.f, sB = 0.f;
#pragma unroll
        for (int nt = 0; nt < 4; nt++) {
            sA += fexp(lA[nt][0] - mA) + fexp(lA[nt][1] - mA);
            sB += fexp(lB[nt][0] - mB) + fexp(lB[nt][1] - mB);
        }
        if (val4) {
            sA += fexp(lA[4][0] - mA) + fexp(lA[4][1] - mA);
            sB += fexp(lB[4][0] - mB) + fexp(lB[4][1] - mB);
        }
        sA += __shfl_xor_sync(0xffffffffu, sA, 1);
        sA += __shfl_xor_sync(0xffffffffu, sA, 2);
        sB += __shfl_xor_sync(0xffffffffu, sB, 1);
        sB += __shfl_xor_sync(0xffffffffu, sB, 2);

        float lseA = 0.f, lseB = 0.f;
        if (cq == 0) { lseA = mA + logf(sA); lseB = mB + logf(sB); }
        lseA = __shfl_sync(0xffffffffu, lseA, lane & ~3);
        lseB = __shfl_sync(0xffffffffu, lseB, lane & ~3);

        const int tglob = t0 + 4 * w + mt;
        float* oA = out + (((size_t)(b * T + tglob)) * U + u0 + g) * C;
        float* oB = oA + 8 * C;                // u + 8
#pragma unroll
        for (int nt = 0; nt < 4; nt++) {
            *(float2*)&oA[nt * 8 + 2 * cq] = make_float2(lA[nt][0] - lseA, lA[nt][1] - lseA);
            *(float2*)&oB[nt * 8 + 2 * cq] = make_float2(lB[nt][0] - lseB, lB[nt][1] - lseB);
        }
        if (val4) {
            *(float2*)&oA[32] = make_float2(lA[4][0] - lseA, lA[4][1] - lseA);
            *(float2*)&oB[32] = make_float2(lB[4][0] - lseB, lB[4][1] - lseB);
        }
    }
}

// ---------------------------------------------------------------------------
extern "C" void kernel_launch(void* const* d_in, const int* in_sizes, int n_in,
                              void* d_out, int out_size) {
    const float* enc    = (const float*)d_in[0];
    const float* dec    = (const float*)d_in[1];
    const float* W_enc  = (const float*)d_in[2];
    const float* b_enc  = (const float*)d_in[3];
    const float* W_pred = (const float*)d_in[4];
    const float* b_pred = (const float*)d_in[5];
    const float* W_out  = (const float*)d_in[6];
    const float* b_out  = (const float*)d_in[7];
    float* out = (float*)d_out;

    static bool attr_set = false;
    if (!attr_set) {
        cudaFuncSetAttribute(k_main, cudaFuncAttributeMaxDynamicSharedMemorySize,
                             SM_FLOATS * 4);
        attr_set = true;
    }

    k_transpose<<<dim3(24, 10, 2), dim3(32, 8)>>>(W_enc, W_pred);
    k_wprep<<<(NT5 * KS * 32 + 255) / 256, 256>>>(W_out);
    k_enc <<<2 * B * (T / 16), 320>>>(enc, b_enc);
    k_pred<<<4 * B * (U / 8),  320>>>(dec, b_pred);
    k_reduce<<<(N_E + 255) / 256, 256>>>();
    k_main<<<B * (T / 16) * (U / 16), 128, SM_FLOATS * 4>>>(b_out, out);
}

// round 16
// speedup vs baseline: 1.1482x; 1.1227x over previous
#include <cuda_runtime.h>

#define B   8
#define EH  768
#define T   512
#define PH  320
#define U   128
#define JH  320
#define C   34
#define NT5 5          // n-tiles (N=40)
#define KS  40         // k8 steps (K=320)
#define PKH 80         // k_pred k-split chunk (4 parts)
#define N_E (B * T * JH)
#define N_P (B * (JH / 4) * U)

typedef unsigned long long u64;
typedef unsigned int u32;

// Scratch (device globals; no runtime allocation allowed)
__device__ float  g_Wt [EH * JH];            // W_enc transposed: [k][j]
__device__ float  g_Wpt[PH * JH];            // W_pred transposed: [k][j]
__device__ float  g_e  [N_E];                // e[b][t][j]
__device__ float4 g_p4p[4][N_P];             // p partials (k-split)
__device__ float4 g_p4 [N_P];                // p interleaved [b][j4][u] (reduced)
__device__ float2 g_Wimg[NT5 * KS * 32];     // W_out tf32 fragment image

// ---- f32x2 packed helpers (projection kernels) ----------------------------
__device__ __forceinline__ u64 pack2(float lo, float hi) {
    u64 r; asm("mov.b64 %0, {%1, %2};" : "=l"(r) : "f"(lo), "f"(hi)); return r;
}
__device__ __forceinline__ void unpack2(u64 v, float& lo, float& hi) {
    asm("mov.b64 {%0, %1}, %2;" : "=f"(lo), "=f"(hi) : "l"(v));
}
#define FMA2(acc, a, b) \
    asm("fma.rn.f32x2 %0, %1, %2, %0;" : "+l"(acc) : "l"(a), "l"(b))
__device__ __forceinline__ void lds_2x64(u64& a, u64& b, const float* p) {
    u32 sa;
    asm("{ .reg .u64 t; cvta.to.shared.u64 t, %1; cvt.u32.u64 %0, t; }"
        : "=r"(sa) : "l"(p));
    asm("ld.shared.v2.u64 {%0, %1}, [%2];" : "=l"(a), "=l"(b) : "r"(sa));
}

// ---- tf32 mma helpers -----------------------------------------------------
__device__ __forceinline__ u32 cvt_tf32(float f) {
    u32 r; asm("cvt.rna.tf32.f32 %0, %1;" : "=r"(r) : "f"(f)); return r;
}
#define MMA_TF32(d, a0, a1, a2, a3, b0, b1)                                   \
    asm("mma.sync.aligned.m16n8k8.row.col.f32.tf32.tf32.f32 "                 \
        "{%0,%1,%2,%3}, {%4,%5,%6,%7}, {%8,%9}, {%0,%1,%2,%3};"               \
        : "+f"((d)[0]), "+f"((d)[1]), "+f"((d)[2]), "+f"((d)[3])              \
        : "r"(a0), "r"(a1), "r"(a2), "r"(a3), "r"(b0), "r"(b1))

// FMA-pipe exp (no MUFU): valid for x <= 0, rel err ~2.4e-6
__device__ __forceinline__ float fexp(float x) {
    x = fmaxf(x, -80.f);
    float y = x * 1.4426950408889634f;
    float r = rintf(y);
    float t = (y - r) * 0.6931471805599453f;
    float p = 8.3333333e-3f;
    p = fmaf(p, t, 4.1666667e-2f);
    p = fmaf(p, t, 1.6666667e-1f);
    p = fmaf(p, t, 5.0e-1f);
    p = fmaf(p, t, 1.0f);
    p = fmaf(p, t, 1.0f);
    int ni = (int)r;
    float sc = __uint_as_float((u32)(ni + 127) << 23);
    return p * sc;
}

// ---------------------------------------------------------------------------
// K0: tiled transpose (coalesced both sides). z=0: W_enc, z=1: W_pred.
// ---------------------------------------------------------------------------
__global__ void k_transpose(const float* __restrict__ W_enc,
                            const float* __restrict__ W_pred) {
    __shared__ float tile[32][33];
    const int which = blockIdx.z;
    const float* src = which ? W_pred : W_enc;
    float* dst = which ? g_Wpt : g_Wt;
    const int Kdim = which ? PH : EH;
    const int k0 = blockIdx.x * 32, j0 = blockIdx.y * 32;
    if (k0 >= Kdim) return;
    const int tx = threadIdx.x, ty = threadIdx.y;
#pragma unroll
    for (int dy = 0; dy < 32; dy += 8)
        tile[ty + dy][tx] = src[(size_t)(j0 + ty + dy) * Kdim + k0 + tx];
    __syncthreads();
#pragma unroll
    for (int dy = 0; dy < 32; dy += 8)
        dst[(size_t)(k0 + ty + dy) * JH + j0 + tx] = tile[tx][ty + dy];
}

// ---------------------------------------------------------------------------
// K0b: bake W_out (padded to 40 rows) into mma B-fragment layout, tf32-rounded.
// ---------------------------------------------------------------------------
__global__ void k_wprep(const float* __restrict__ W_out) {
    int i = blockIdx.x * blockDim.x + threadIdx.x;
    if (i >= NT5 * KS * 32) return;
    int lane = i & 31;
    int ks = (i >> 5) % KS;
    int nt = i / (KS * 32);
    int g = lane >> 2, cq = lane & 3;
    int n = nt * 8 + g;
    int k0 = ks * 8;
    float v0 = (n < C) ? W_out[n * JH + k0 + cq]     : 0.f;
    float v1 = (n < C) ? W_out[n * JH + k0 + cq + 4] : 0.f;
    g_Wimg[i] = make_float2(__uint_as_float(cvt_tf32(v0)),
                            __uint_as_float(cvt_tf32(v1)));
}

// ---------------------------------------------------------------------------
// K1: e[b][t][j] = sum_k enc[b][k][t] * W_enc[j][k] + b_enc[j]
// EXACT R12 version: one CTA = (b, 16 t), 320 threads = j, direct g_e write.
// ---------------------------------------------------------------------------
__global__ __launch_bounds__(320) void k_enc(const float* __restrict__ enc,
                                             const float* __restrict__ b_enc) {
    __shared__ float enc_s[EH * 16];   // 48 KB, [k][t]
    const int b = blockIdx.x >> 5, t0 = (blockIdx.x & 31) << 4, tid = threadIdx.x;
    const float* src = enc + (size_t)b * EH * T + t0;
    for (int i = tid; i < EH * 16; i += 320) {
        int k = i >> 4, t = i & 15;
        enc_s[i] = src[k * T + t];
    }
    __syncthreads();

    const int j = tid;
    u64 acc[8];
    { float bj = b_enc[j]; u64 b2 = pack2(bj, bj);
#pragma unroll
      for (int m = 0; m < 8; m++) acc[m] = b2; }

#pragma unroll 1
    for (int k = 0; k < EH; k += 4) {
#pragma unroll
        for (int kk = 0; kk < 4; kk++) {
            float w = g_Wt[(k + kk) * JH + j];
            u64 wp = pack2(w, w);
            const float* er = &enc_s[(k + kk) * 16];
            u64 e0, e1, e2, e3, e4, e5, e6, e7;
            lds_2x64(e0, e1, er);
            lds_2x64(e2, e3, er + 4);
            lds_2x64(e4, e5, er + 8);
            lds_2x64(e6, e7, er + 12);
            FMA2(acc[0], wp, e0);  FMA2(acc[1], wp, e1);
            FMA2(acc[2], wp, e2);  FMA2(acc[3], wp, e3);
            FMA2(acc[4], wp, e4);  FMA2(acc[5], wp, e5);
            FMA2(acc[6], wp, e6);  FMA2(acc[7], wp, e7);
        }
    }

    float* dst = g_e + ((size_t)b * T + t0) * JH + j;
#pragma unroll
    for (int m = 0; m < 8; m++) {
        float lo, hi; unpack2(acc[m], lo, hi);
        dst[(2 * m) * JH] = lo; dst[(2 * m + 1) * JH] = hi;
    }
}

// ---------------------------------------------------------------------------
// K2: p projection, k-split x4 (measured win). CTA = (part, b, 8 u).
// ---------------------------------------------------------------------------
__global__ __launch_bounds__(320) void k_pred(const float* __restrict__ dec,
                                              const float* __restrict__ b_pred) {
    __shared__ float dec_s[PKH * 8];
    const int bx = blockIdx.x;
    const int part = bx >> 7;
    const int rem  = bx & 127;
    const int b = rem >> 4, u0 = (rem & 15) << 3, tid = threadIdx.x;
    const int kbase = part * PKH;

    const float* src = dec + (size_t)b * PH * U + (size_t)kbase * U + u0;
    for (int i = tid; i < PKH * 8; i += 320) {
        int k = i >> 3, uu = i & 7;
        dec_s[i] = src[k * U + uu];
    }
    __syncthreads();

    const int j = tid;
    u64 acc[4];
    {
        float bj = part ? 0.f : b_pred[j];
        u64 b2 = pack2(bj, bj);
#pragma unroll
        for (int m = 0; m < 4; m++) acc[m] = b2;
    }

#pragma unroll 1
    for (int k = 0; k < PKH; k += 4) {
#pragma unroll
        for (int kk = 0; kk < 4; kk++) {
            float w = g_Wpt[(kbase + k + kk) * JH + j];
            u64 wp = pack2(w, w);
            const float* dr = &dec_s[(k + kk) * 8];
            u64 d0, d1, d2, d3;
            lds_2x64(d0, d1, dr);
            lds_2x64(d2, d3, dr + 4);
            FMA2(acc[0], wp, d0);  FMA2(acc[1], wp, d1);
            FMA2(acc[2], wp, d2);  FMA2(acc[3], wp, d3);
        }
    }

    float* p4f = (float*)g_p4p[part];
    const int base = ((b * (JH / 4) + (j >> 2)) * U) * 4 + (j & 3);
#pragma unroll
    for (int m = 0; m < 4; m++) {
        float lo, hi; unpack2(acc[m], lo, hi);
        p4f[base + (u0 + 2 * m) * 4]     = lo;
        p4f[base + (u0 + 2 * m + 1) * 4] = hi;
    }
}

// ---------------------------------------------------------------------------
// K2b: reduce ONLY the p partials (small: 81920 float4)
// ---------------------------------------------------------------------------
__global__ void k_reduce_p() {
    int i = blockIdx.x * 256 + threadIdx.x;
    if (i < N_P) {
        float4 a = g_p4p[0][i], b = g_p4p[1][i], c = g_p4p[2][i], d = g_p4p[3][i];
        g_p4[i] = make_float4(a.x + b.x + c.x + d.x, a.y + b.y + c.y + d.y,
                              a.z + b.z + c.z + d.z, a.w + b.w + c.w + d.w);
    }
}

// ---------------------------------------------------------------------------
// K3 (main): EXACT R12 tensor-core joint. CTA = 16t x 16u, 128 thr / 4 warps.
// ---------------------------------------------------------------------------
#define ESTRIDE 324
#define SM_W 0
#define SM_E (NT5 * KS * 32 * 2)               // 12800 floats
#define SM_P (SM_E + 16 * ESTRIDE)
#define SM_FLOATS (SM_P + 16 * ESTRIDE)        // 23168 floats = 92672 B

__global__ __launch_bounds__(128) void k_main(const float* __restrict__ b_out,
                                              float* __restrict__ out) {
    extern __shared__ float sm[];
    float* W_s = sm + SM_W;
    float* e_s = sm + SM_E;
    float* p_s = sm + SM_P;

    const int tid = threadIdx.x;
    const int lane = tid & 31, w = tid >> 5;
    const int g = lane >> 2, cq = lane & 3;

    const int bx = blockIdx.x;                 // 2048 = 8b x 32tt x 8ut
    const int b  = bx >> 8;
    const int t0 = ((bx >> 3) & 31) << 4;
    const int u0 = (bx & 7) << 4;

    // ---- stage W frags, e rows, p rows ----
    {
        const float4* Wd = (const float4*)g_Wimg;
        float4* Ws4 = (float4*)W_s;
        for (int i = tid; i < NT5 * KS * 16; i += 128) Ws4[i] = Wd[i];

        const float* esrc = g_e + ((size_t)b * T + t0) * JH;
        for (int i = tid; i < 16 * 80; i += 128) {
            int r = i / 80, q = i % 80;
            ((float4*)&e_s[r * ESTRIDE])[q] = ((const float4*)&esrc[(size_t)r * JH])[q];
        }
        const float4* psrc = g_p4 + (size_t)b * (JH / 4) * U + u0;
        for (int i = tid; i < 16 * 80; i += 128) {
            int q = i >> 4, r = i & 15;        // q = j4, r = u
            ((float4*)&p_s[r * ESTRIDE])[q] = psrc[q * U + r];
        }
    }
    __syncthreads();

    float acc[4][NT5][4];
#pragma unroll
    for (int mt = 0; mt < 4; mt++)
#pragma unroll
        for (int nt = 0; nt < NT5; nt++)
#pragma unroll
            for (int i = 0; i < 4; i++) acc[mt][nt][i] = 0.f;

    // ---- main k loop ----
#pragma unroll 1
    for (int ks = 0; ks < KS; ks++) {
        const int k0 = ks * 8;
        u32 bf[NT5][2];
#pragma unroll
        for (int nt = 0; nt < NT5; nt++) {
            float2 bv = *(const float2*)&W_s[((nt * KS + ks) * 32 + lane) * 2];
            bf[nt][0] = __float_as_uint(bv.x);
            bf[nt][1] = __float_as_uint(bv.y);
        }
#pragma unroll
        for (int mt = 0; mt < 4; mt++) {
            const float* er  = &e_s[(4 * w + mt) * ESTRIDE + k0];
            const float* pr0 = &p_s[g * ESTRIDE + k0];
            const float* pr1 = &p_s[(g + 8) * ESTRIDE + k0];
            float e0 = er[cq], e1 = er[cq + 4];
            u32 a0 = cvt_tf32(fmaxf(e0 + pr0[cq],     0.f));   // (r, cq)
            u32 a1 = cvt_tf32(fmaxf(e0 + pr1[cq],     0.f));   // (r+8, cq)
            u32 a2 = cvt_tf32(fmaxf(e1 + pr0[cq + 4], 0.f));   // (r, cq+4)
            u32 a3 = cvt_tf32(fmaxf(e1 + pr1[cq + 4], 0.f));   // (r+8, cq+4)
#pragma unroll
            for (int nt = 0; nt < NT5; nt++)
                MMA_TF32(acc[mt][nt], a0, a1, a2, a3, bf[nt][0], bf[nt][1]);
        }
    }

    // ---- epilogue: bias + masked log_softmax + store ----
    const bool val4 = (cq == 0);               // nt=4 classes {32,33} only on cq==0
    float bo[NT5][2];
#pragma unroll
    for (int nt = 0; nt < NT5; nt++) {
        int cls = nt * 8 + 2 * cq;
        bo[nt][0] = (cls     < C) ? __ldg(&b_out[cls])     : 0.f;
        bo[nt][1] = (cls + 1 < C) ? __ldg(&b_out[cls + 1]) : 0.f;
    }

#pragma unroll 1
    for (int mt = 0; mt < 4; mt++) {
        float lA[NT5][2], lB[NT5][2];
#pragma unroll
        for (int nt = 0; nt < NT5; nt++) {
            lA[nt][0] = acc[mt][nt][0] + bo[nt][0];
            lA[nt][1] = acc[mt][nt][1] + bo[nt][1];
            lB[nt][0] = acc[mt][nt][2] + bo[nt][0];
            lB[nt][1] = acc[mt][nt][3] + bo[nt][1];
        }
        float mA = -1e30f, mB = -1e30f;
#pragma unroll
        for (int nt = 0; nt < 4; nt++) {
            mA = fmaxf(mA, fmaxf(lA[nt][0], lA[nt][1]));
            mB = fmaxf(mB, fmaxf(lB[nt][0], lB[nt][1]));
        }
        if (val4) {
            mA = fmaxf(mA, fmaxf(lA[4][0], lA[4][1]));
            mB = fmaxf(mB, fmaxf(lB[4][0], lB[4][1]));
        }
        mA = fmaxf(mA, __shfl_xor_sync(0xffffffffu, mA, 1));
        mA = fmaxf(mA, __shfl_xor_sync(0xffffffffu, mA, 2));
        mB = fmaxf(mB, __shfl_xor_sync(0xffffffffu, mB, 1));
        mB = fmaxf(mB, __shfl_xor_sync(0xffffffffu, mB, 2));

        float sA = 0.f, sB = 0.f;
#pragma unroll
        for (int nt = 0; nt < 4; nt++) {
            sA += fexp(lA[nt][0] - mA) + fexp(lA[nt][1] - mA);
            sB += fexp(lB[nt][0] - mB) + fexp(lB[nt][1] - mB);
        }
        if (val4) {
            sA += fexp(lA[4][0] - mA) + fexp(lA[4][1] - mA);
            sB += fexp(lB[4][0] - mB) + fexp(lB[4][1] - mB);
        }
        sA += __shfl_xor_sync(0xffffffffu, sA, 1);
        sA += __shfl_xor_sync(0xffffffffu, sA, 2);
        sB += __shfl_xor_sync(0xffffffffu, sB, 1);
        sB += __shfl_xor_sync(0xffffffffu, sB, 2);

        float lseA = 0.f, lseB = 0.f;
        if (cq == 0) { lseA = mA + logf(sA); lseB = mB + logf(sB); }
        lseA = __shfl_sync(0xffffffffu, lseA, lane & ~3);
        lseB = __shfl_sync(0xffffffffu, lseB, lane & ~3);

        const int tglob = t0 + 4 * w + mt;
        float* oA = out + (((size_t)(b * T + tglob)) * U + u0 + g) * C;
        float* oB = oA + 8 * C;                // u + 8
#pragma unroll
        for (int nt = 0; nt < 4; nt++) {
            *(float2*)&oA[nt * 8 + 2 * cq] = make_float2(lA[nt][0] - lseA, lA[nt][1] - lseA);
            *(float2*)&oB[nt * 8 + 2 * cq] = make_float2(lB[nt][0] - lseB, lB[nt][1] - lseB);
        }
        if (val4) {
            *(float2*)&oA[32] = make_float2(lA[4][0] - lseA, lA[4][1] - lseA);
            *(float2*)&oB[32] = make_float2(lB[4][0] - lseB, lB[4][1] - lseB);
        }
    }
}

// ---------------------------------------------------------------------------
extern "C" void kernel_launch(void* const* d_in, const int* in_sizes, int n_in,
                              void* d_out, int out_size) {
    const float* enc    = (const float*)d_in[0];
    const float* dec    = (const float*)d_in[1];
    const float* W_enc  = (const float*)d_in[2];
    const float* b_enc  = (const float*)d_in[3];
    const float* W_pred = (const float*)d_in[4];
    const float* b_pred = (const float*)d_in[5];
    const float* W_out  = (const float*)d_in[6];
    const float* b_out  = (const float*)d_in[7];
    float* out = (float*)d_out;

    static bool attr_set = false;
    if (!attr_set) {
        cudaFuncSetAttribute(k_main, cudaFuncAttributeMaxDynamicSharedMemorySize,
                             SM_FLOATS * 4);
        attr_set = true;
    }

    k_transpose<<<dim3(24, 10, 2), dim3(32, 8)>>>(W_enc, W_pred);
    k_wprep<<<(NT5 * KS * 32 + 255) / 256, 256>>>(W_out);
    k_enc <<<B * (T / 16), 320>>>(enc, b_enc);
    k_pred<<<4 * B * (U / 8),  320>>>(dec, b_pred);
    k_reduce_p<<<(N_P + 255) / 256, 256>>>();
    k_main<<<B * (T / 16) * (U / 16), 128, SM_FLOATS * 4>>>(b_out, out);
}